// round 2
// baseline (speedup 1.0000x reference)
#include <cuda_runtime.h>
#include <math.h>
#include <stdint.h>

#define B 128
#define T 512
#define E 256
#define H 256
#define DA 25
#define HEADS 5

// ---------------- device scratch (static, no allocs) ----------------
__device__ float g_px[(size_t)2 * T * B * 1024];   // [dir][t][b][4H]  512MB
__device__ float g_hstate[2 * 2 * B * H];          // [buf][dir][b][H]
__device__ float g_Hc[(size_t)B * T * 2 * H];      // [b][t][512]  128MB
__device__ float g_s[B * HEADS * T];               // [b][h][t]
__device__ float g_A[B * HEADS * T];               // [b][h][t]
__device__ float g_pp[B];
__device__ unsigned g_bar[8];

__device__ __forceinline__ float sigf(float x) { return 1.0f / (1.0f + expf(-x)); }

// ---------------- init: zero Hc, hstate, barriers -------------------
__global__ void k_init() {
    size_t i = (size_t)blockIdx.x * blockDim.x + threadIdx.x;
    size_t stride = (size_t)gridDim.x * blockDim.x;
    size_t nHc = (size_t)B * T * 2 * H;
    for (size_t p = i; p < nHc; p += stride) g_Hc[p] = 0.0f;
    for (size_t p = i; p < (size_t)2 * 2 * B * H; p += stride) g_hstate[p] = 0.0f;
    if (i < 8) g_bar[i] = 0u;
}

// ---------------- input projection GEMM (gather fused) --------------
// px[d][m][n] = sum_k emb[wid(m,d)][k] * W_ih[n][k] + bias[n],  m=t*128+b
__global__ void k_px(const int* __restrict__ wid, const int* __restrict__ lens,
                     const float* __restrict__ emb,
                     const float* __restrict__ Wf, const float* __restrict__ bf,
                     const float* __restrict__ Wb, const float* __restrict__ bb)
{
    const int d = blockIdx.z;
    const float* __restrict__ Wih  = d ? Wb : Wf;
    const float* __restrict__ bias = d ? bb : bf;
    const int n0 = blockIdx.x * 64;
    const int m0 = blockIdx.y * 64;

    __shared__ float As[16][68];
    __shared__ float Bs[16][68];
    __shared__ int   sw[64];

    const int tid = threadIdx.x;
    if (tid < 64) {
        int m = m0 + tid;
        int b = m & 127, t = m >> 7;
        int tt = t;
        if (d) { int L = lens[b]; tt = L - 1 - t; if (tt < 0) tt = 0; }
        sw[tid] = wid[b * T + tt];
    }
    __syncthreads();

    const int r  = tid >> 2, kq = tid & 3;
    const int tx = tid & 15, ty = tid >> 4;
    const float* __restrict__ Arow = emb + (size_t)sw[r] * E;
    const float* __restrict__ Brow = Wih + (size_t)(n0 + r) * E;

    float acc[4][4] = {};

    for (int k0 = 0; k0 < E; k0 += 16) {
        float4 av = *(const float4*)&Arow[k0 + kq * 4];
        float4 bv = *(const float4*)&Brow[k0 + kq * 4];
        As[kq * 4 + 0][r] = av.x; As[kq * 4 + 1][r] = av.y;
        As[kq * 4 + 2][r] = av.z; As[kq * 4 + 3][r] = av.w;
        Bs[kq * 4 + 0][r] = bv.x; Bs[kq * 4 + 1][r] = bv.y;
        Bs[kq * 4 + 2][r] = bv.z; Bs[kq * 4 + 3][r] = bv.w;
        __syncthreads();
        #pragma unroll
        for (int kk = 0; kk < 16; kk++) {
            float4 a  = *(const float4*)&As[kk][ty * 4];
            float4 b4 = *(const float4*)&Bs[kk][tx * 4];
            acc[0][0] = fmaf(a.x, b4.x, acc[0][0]); acc[0][1] = fmaf(a.x, b4.y, acc[0][1]);
            acc[0][2] = fmaf(a.x, b4.z, acc[0][2]); acc[0][3] = fmaf(a.x, b4.w, acc[0][3]);
            acc[1][0] = fmaf(a.y, b4.x, acc[1][0]); acc[1][1] = fmaf(a.y, b4.y, acc[1][1]);
            acc[1][2] = fmaf(a.y, b4.z, acc[1][2]); acc[1][3] = fmaf(a.y, b4.w, acc[1][3]);
            acc[2][0] = fmaf(a.z, b4.x, acc[2][0]); acc[2][1] = fmaf(a.z, b4.y, acc[2][1]);
            acc[2][2] = fmaf(a.z, b4.z, acc[2][2]); acc[2][3] = fmaf(a.z, b4.w, acc[2][3]);
            acc[3][0] = fmaf(a.w, b4.x, acc[3][0]); acc[3][1] = fmaf(a.w, b4.y, acc[3][1]);
            acc[3][2] = fmaf(a.w, b4.z, acc[3][2]); acc[3][3] = fmaf(a.w, b4.w, acc[3][3]);
        }
        __syncthreads();
    }

    float b0v = bias[n0 + tx * 4 + 0];
    float b1v = bias[n0 + tx * 4 + 1];
    float b2v = bias[n0 + tx * 4 + 2];
    float b3v = bias[n0 + tx * 4 + 3];
    const size_t pxbase = (size_t)d * T * B * 1024;
    #pragma unroll
    for (int i = 0; i < 4; i++) {
        int m = m0 + ty * 4 + i;
        float4 o;
        o.x = acc[i][0] + b0v; o.y = acc[i][1] + b1v;
        o.z = acc[i][2] + b2v; o.w = acc[i][3] + b3v;
        *(float4*)&g_px[pxbase + (size_t)m * 1024 + n0 + tx * 4] = o;
    }
}

// ---------------- persistent LSTM recurrence ------------------------
// grid: 128 blocks = 2 dirs * 16 j-tiles(16) * 4 batch-groups(32); 128 threads.
// thread = (bq 0..7, jl 0..15): owns hidden unit j0+jl for 4 batches.
__global__ void k_lstm(const float* __restrict__ Whf, const float* __restrict__ Whb,
                       const int* __restrict__ lens)
{
    extern __shared__ float sm[];
    float* Wsh = sm;                 // [4][16][260] = 16640 floats
    float* hsh = sm + 16640;         // [32][260]    = 8320 floats

    const int tid = threadIdx.x;
    const int d   = blockIdx.x >> 6;
    const int rem = blockIdx.x & 63;
    const int jb  = rem >> 2, bg = rem & 3;
    const int j0  = jb * 16, b0 = bg * 32;
    const float* __restrict__ Whh = d ? Whb : Whf;

    // load W_hh tile: rows g*H + (j0..j0+15), all 256 k
    for (int idx = tid; idx < 4 * 16 * 64; idx += 128) {
        int g = idx >> 10;
        int jj = (idx >> 6) & 15;
        int col = idx & 63;
        float4 w = *(const float4*)&Whh[(size_t)(g * H + j0 + jj) * H + col * 4];
        *(float4*)&Wsh[(g * 16 + jj) * 260 + col * 4] = w;
    }

    const int jl = tid & 15, bq = tid >> 4;
    int tlen[4];
    int maxlen = 0;
    for (int i = 0; i < 32; i++) { int L = lens[b0 + i]; if (L > maxlen) maxlen = L; }
    #pragma unroll
    for (int bi = 0; bi < 4; bi++) tlen[bi] = lens[b0 + bq * 4 + bi];

    float c[4] = {0.f, 0.f, 0.f, 0.f};
    const size_t pxbase = (size_t)d * T * B * 1024;
    const unsigned barid = d * 4 + bg;
    __syncthreads();

    for (int t = 0; t < maxlen; t++) {
        const int rb = t & 1;
        const float* hsrc = g_hstate + ((size_t)(rb * 2 + d) * B + b0) * H;
        for (int idx = tid; idx < 32 * 64; idx += 128) {
            int row = idx >> 6, col = idx & 63;
            float4 hv = __ldcg((const float4*)(hsrc + row * H + col * 4));
            *(float4*)&hsh[row * 260 + col * 4] = hv;
        }
        __syncthreads();

        float acc[4][4] = {};
        #pragma unroll 2
        for (int k = 0; k < H; k += 4) {
            float4 w0 = *(const float4*)&Wsh[(jl) * 260 + k];
            float4 w1 = *(const float4*)&Wsh[(16 + jl) * 260 + k];
            float4 w2 = *(const float4*)&Wsh[(32 + jl) * 260 + k];
            float4 w3 = *(const float4*)&Wsh[(48 + jl) * 260 + k];
            float4 h0 = *(const float4*)&hsh[(bq * 4 + 0) * 260 + k];
            float4 h1 = *(const float4*)&hsh[(bq * 4 + 1) * 260 + k];
            float4 h2 = *(const float4*)&hsh[(bq * 4 + 2) * 260 + k];
            float4 h3 = *(const float4*)&hsh[(bq * 4 + 3) * 260 + k];
            #define DOT4(g_, hv_, bi_) \
                acc[g_][bi_] = fmaf(w##g_.x, hv_.x, acc[g_][bi_]); \
                acc[g_][bi_] = fmaf(w##g_.y, hv_.y, acc[g_][bi_]); \
                acc[g_][bi_] = fmaf(w##g_.z, hv_.z, acc[g_][bi_]); \
                acc[g_][bi_] = fmaf(w##g_.w, hv_.w, acc[g_][bi_]);
            DOT4(0, h0, 0) DOT4(0, h1, 1) DOT4(0, h2, 2) DOT4(0, h3, 3)
            DOT4(1, h0, 0) DOT4(1, h1, 1) DOT4(1, h2, 2) DOT4(1, h3, 3)
            DOT4(2, h0, 0) DOT4(2, h1, 1) DOT4(2, h2, 2) DOT4(2, h3, 3)
            DOT4(3, h0, 0) DOT4(3, h1, 1) DOT4(3, h2, 2) DOT4(3, h3, 3)
            #undef DOT4
        }

        const int wb = (t + 1) & 1;
        #pragma unroll
        for (int bi = 0; bi < 4; bi++) {
            if (t < tlen[bi]) {
                int b = b0 + bq * 4 + bi;
                const float* pxp = g_px + pxbase + ((size_t)t * B + b) * 1024 + j0 + jl;
                float iv = sigf (acc[0][bi] + __ldg(pxp));
                float fv = sigf (acc[1][bi] + __ldg(pxp + 256));
                float gv = tanhf(acc[2][bi] + __ldg(pxp + 512));
                float ov = sigf (acc[3][bi] + __ldg(pxp + 768));
                c[bi] = fv * c[bi] + iv * gv;
                float hv = ov * tanhf(c[bi]);
                g_hstate[((size_t)(wb * 2 + d) * B + b) * H + j0 + jl] = hv;
                int pos = d ? (tlen[bi] - 1 - t) : t;
                g_Hc[((size_t)b * T + pos) * (2 * H) + d * H + j0 + jl] = hv;
            }
        }

        __threadfence();
        __syncthreads();
        if (tid == 0) {
            atomicAdd(&g_bar[barid], 1u);
            unsigned target = 16u * (unsigned)(t + 1);
            while (*((volatile unsigned*)&g_bar[barid]) < target) {}
            __threadfence();
        }
        __syncthreads();
    }
}

// ---------------- attention scores: s = tanh(Hc W_s1^T) W_s2^T ------
__global__ void k_scores(const float* __restrict__ Ws1, const float* __restrict__ Ws2)
{
    int wp = (blockIdx.x * blockDim.x + threadIdx.x) >> 5;
    int lane = threadIdx.x & 31;
    if (wp >= B * T) return;
    int b = wp >> 9, t = wp & 511;
    const float* hc = g_Hc + ((size_t)b * T + t) * 512;
    float hv[16];
    #pragma unroll
    for (int kk = 0; kk < 16; kk++) hv[kk] = hc[lane + kk * 32];
    float u[DA];
    #pragma unroll
    for (int a = 0; a < DA; a++) {
        const float* w = Ws1 + a * 512;
        float s = 0.f;
        #pragma unroll
        for (int kk = 0; kk < 16; kk++) s = fmaf(hv[kk], __ldg(&w[lane + kk * 32]), s);
        #pragma unroll
        for (int off = 16; off; off >>= 1) s += __shfl_xor_sync(0xffffffffu, s, off);
        u[a] = tanhf(s);
    }
    if (lane < HEADS) {
        float s = 0.f;
        #pragma unroll
        for (int a = 0; a < DA; a++) s = fmaf(u[a], __ldg(&Ws2[lane * DA + a]), s);
        g_s[((size_t)b * HEADS + lane) * T + t] = s;
    }
}

// ---------------- masked softmax over time, per (b,head) ------------
__global__ void k_softmax(const int* __restrict__ lens)
{
    int b = blockIdx.x / HEADS, h = blockIdx.x % HEADS;
    int t = threadIdx.x;               // 512
    int L = lens[b];
    __shared__ float red[512];
    float sv = (t < L) ? g_s[((size_t)b * HEADS + h) * T + t] : -3.0e38f;
    red[t] = sv; __syncthreads();
    for (int off = 256; off; off >>= 1) { if (t < off) red[t] = fmaxf(red[t], red[t + off]); __syncthreads(); }
    float m = red[0]; __syncthreads();
    float e = (t < L) ? expf(sv - m) : 0.0f;
    red[t] = e; __syncthreads();
    for (int off = 256; off; off >>= 1) { if (t < off) red[t] += red[t + off]; __syncthreads(); }
    g_A[((size_t)b * HEADS + h) * T + t] = e / red[0];
}

// ---------------- M = A @ Hc  ->  sentence embeddings ---------------
__global__ void k_M(float* __restrict__ out)
{
    int b = blockIdx.x;
    int d = threadIdx.x;               // 512
    __shared__ float As[HEADS * T];
    for (int i = d; i < HEADS * T; i += 512) As[i] = g_A[(size_t)b * HEADS * T + i];
    __syncthreads();
    float acc[HEADS] = {};
    const float* hcb = g_Hc + (size_t)b * T * 512;
    for (int t = 0; t < T; t++) {
        float hc = hcb[(size_t)t * 512 + d];
        #pragma unroll
        for (int h = 0; h < HEADS; h++) acc[h] = fmaf(As[h * T + t], hc, acc[h]);
    }
    #pragma unroll
    for (int h = 0; h < HEADS; h++)
        out[(size_t)b * (HEADS * 2 * H) + h * 512 + d] = acc[h];
}

// ---------------- penalty -------------------------------------------
__global__ void k_penal1()
{
    int b = blockIdx.x;
    int tid = threadIdx.x;             // 256
    __shared__ float As[HEADS * T];
    __shared__ float red[256];
    for (int i = tid; i < HEADS * T; i += 256) As[i] = g_A[(size_t)b * HEADS * T + i];
    __syncthreads();
    float tot = 0.0f;
    for (int h = 0; h < HEADS; h++) {
        for (int g = 0; g < HEADS; g++) {
            if (h == g) continue;
            float p = 0.0f;
            for (int t = tid; t < T; t += 256) p = fmaf(As[h * T + t], As[g * T + t], p);
            red[tid] = p; __syncthreads();
            for (int off = 128; off; off >>= 1) { if (tid < off) red[tid] += red[tid + off]; __syncthreads(); }
            if (tid == 0) tot += red[0] * red[0];
            __syncthreads();
        }
    }
    if (tid == 0) g_pp[b] = tot;
}

__global__ void k_penal2(float* __restrict__ out, int out_size)
{
    __shared__ float red[128];
    red[threadIdx.x] = g_pp[threadIdx.x];
    __syncthreads();
    for (int off = 64; off; off >>= 1) { if (threadIdx.x < off) red[threadIdx.x] += red[threadIdx.x + off]; __syncthreads(); }
    if (threadIdx.x == 0) out[out_size - 1] = red[0] / (float)B;
}

// ---------------- launch --------------------------------------------
extern "C" void kernel_launch(void* const* d_in, const int* in_sizes, int n_in,
                              void* d_out, int out_size)
{
    const int*   word_ids = (const int*)  d_in[0];
    const int*   lens     = (const int*)  d_in[1];
    const float* emb      = (const float*)d_in[2];
    const float* Wihf     = (const float*)d_in[3];
    const float* Whhf     = (const float*)d_in[4];
    const float* bf       = (const float*)d_in[5];
    const float* Wihb     = (const float*)d_in[6];
    const float* Whhb     = (const float*)d_in[7];
    const float* bb       = (const float*)d_in[8];
    const float* Ws1      = (const float*)d_in[9];
    const float* Ws2      = (const float*)d_in[10];
    float* out = (float*)d_out;

    k_init<<<2048, 256>>>();

    dim3 gpx(16, 1024, 2);
    k_px<<<gpx, 256>>>(word_ids, lens, emb, Wihf, bf, Wihb, bb);

    cudaFuncSetAttribute(k_lstm, cudaFuncAttributeMaxDynamicSharedMemorySize, 24960 * 4);
    k_lstm<<<128, 128, 24960 * 4>>>(Whhf, Whhb, lens);

    k_scores<<<(B * T) / 8, 256>>>(Ws1, Ws2);
    k_softmax<<<B * HEADS, 512>>>(lens);
    k_M<<<B, 512>>>(out);
    k_penal1<<<B, 256>>>();
    k_penal2<<<1, 128>>>(out, out_size);
}

// round 3
// speedup vs baseline: 1.9317x; 1.9317x over previous
#include <cuda_runtime.h>
#include <math.h>
#include <stdint.h>

#define B 128
#define T 512
#define E 256
#define H 256
#define DA 25
#define HEADS 5
#define V 2080

typedef unsigned long long ull;

// ---------------- device scratch (static, no allocs) ----------------
__device__ float g_P[(size_t)2 * V * 1024];        // [dir][v][4H]  17MB (L2-resident)
__device__ float g_hstate[2 * 2 * B * H];          // [buf][dir][b][H]
__device__ float g_Hc[(size_t)B * T * 2 * H];      // [b][t][512]  128MB
__device__ float g_s[B * HEADS * T];               // [b][h][t]
__device__ float g_A[B * HEADS * T];               // [b][h][t]
__device__ float g_pp[B];
__device__ unsigned g_bar[8];

__device__ __forceinline__ float sigf(float x) { return 1.0f / (1.0f + expf(-x)); }

__device__ __forceinline__ ull pack2(float lo, float hi) {
    ull r;
    asm("mov.b64 %0, {%1,%2};" : "=l"(r) : "f"(lo), "f"(hi));
    return r;
}
__device__ __forceinline__ void unpack2(ull v, float& lo, float& hi) {
    asm("mov.b64 {%0,%1}, %2;" : "=f"(lo), "=f"(hi) : "l"(v));
}
__device__ __forceinline__ ull fma2(ull a, ull b, ull c) {
    ull d;
    asm("fma.rn.f32x2 %0, %1, %2, %3;" : "=l"(d) : "l"(a), "l"(b), "l"(c));
    return d;
}

// ---------------- init: zero Hc, hstate, barriers -------------------
__global__ void k_init() {
    size_t i = (size_t)blockIdx.x * blockDim.x + threadIdx.x;
    size_t stride = (size_t)gridDim.x * blockDim.x;
    size_t nHc = (size_t)B * T * 2 * H;
    for (size_t p = i; p < nHc; p += stride) g_Hc[p] = 0.0f;
    for (size_t p = i; p < (size_t)2 * 2 * B * H; p += stride) g_hstate[p] = 0.0f;
    if (i < 8) g_bar[i] = 0u;
}

// ---------------- vocab projection: P[d][v][n] = emb[v] . W_ih[n] + b[n]
__global__ void k_P(const float* __restrict__ emb,
                    const float* __restrict__ Wf, const float* __restrict__ bf,
                    const float* __restrict__ Wb, const float* __restrict__ bb)
{
    const int d = blockIdx.z;
    const float* __restrict__ Wih  = d ? Wb : Wf;
    const float* __restrict__ bias = d ? bb : bf;
    const int n0 = blockIdx.x * 64;
    const int m0 = blockIdx.y * 64;

    __shared__ float As[16][68];
    __shared__ float Bs[16][68];

    const int tid = threadIdx.x;
    const int r  = tid >> 2, kq = tid & 3;
    const int tx = tid & 15, ty = tid >> 4;
    int v = m0 + r; if (v >= V) v = 0;
    const float* __restrict__ Arow = emb + (size_t)v * E;
    const float* __restrict__ Brow = Wih + (size_t)(n0 + r) * E;

    float acc[4][4] = {};

    for (int k0 = 0; k0 < E; k0 += 16) {
        float4 av = *(const float4*)&Arow[k0 + kq * 4];
        float4 bv = *(const float4*)&Brow[k0 + kq * 4];
        As[kq * 4 + 0][r] = av.x; As[kq * 4 + 1][r] = av.y;
        As[kq * 4 + 2][r] = av.z; As[kq * 4 + 3][r] = av.w;
        Bs[kq * 4 + 0][r] = bv.x; Bs[kq * 4 + 1][r] = bv.y;
        Bs[kq * 4 + 2][r] = bv.z; Bs[kq * 4 + 3][r] = bv.w;
        __syncthreads();
        #pragma unroll
        for (int kk = 0; kk < 16; kk++) {
            float4 a  = *(const float4*)&As[kk][ty * 4];
            float4 b4 = *(const float4*)&Bs[kk][tx * 4];
            acc[0][0] = fmaf(a.x, b4.x, acc[0][0]); acc[0][1] = fmaf(a.x, b4.y, acc[0][1]);
            acc[0][2] = fmaf(a.x, b4.z, acc[0][2]); acc[0][3] = fmaf(a.x, b4.w, acc[0][3]);
            acc[1][0] = fmaf(a.y, b4.x, acc[1][0]); acc[1][1] = fmaf(a.y, b4.y, acc[1][1]);
            acc[1][2] = fmaf(a.y, b4.z, acc[1][2]); acc[1][3] = fmaf(a.y, b4.w, acc[1][3]);
            acc[2][0] = fmaf(a.z, b4.x, acc[2][0]); acc[2][1] = fmaf(a.z, b4.y, acc[2][1]);
            acc[2][2] = fmaf(a.z, b4.z, acc[2][2]); acc[2][3] = fmaf(a.z, b4.w, acc[2][3]);
            acc[3][0] = fmaf(a.w, b4.x, acc[3][0]); acc[3][1] = fmaf(a.w, b4.y, acc[3][1]);
            acc[3][2] = fmaf(a.w, b4.z, acc[3][2]); acc[3][3] = fmaf(a.w, b4.w, acc[3][3]);
        }
        __syncthreads();
    }

    float b0v = bias[n0 + tx * 4 + 0];
    float b1v = bias[n0 + tx * 4 + 1];
    float b2v = bias[n0 + tx * 4 + 2];
    float b3v = bias[n0 + tx * 4 + 3];
    const size_t pbase = (size_t)d * V * 1024;
    #pragma unroll
    for (int i = 0; i < 4; i++) {
        int m = m0 + ty * 4 + i;
        if (m < V) {
            float4 o;
            o.x = acc[i][0] + b0v; o.y = acc[i][1] + b1v;
            o.z = acc[i][2] + b2v; o.w = acc[i][3] + b3v;
            *(float4*)&g_P[pbase + (size_t)m * 1024 + n0 + tx * 4] = o;
        }
    }
}

// ---------------- persistent LSTM recurrence ------------------------
// 128 blocks = 2 dirs * 16 j-tiles(16) * 4 batch-groups(32); 128 threads.
// thread = (bq 0..15 -> 2 batches, jp 0..7 -> j-pair). f32x2 packed over j.
__global__ void k_lstm(const float* __restrict__ Whf, const float* __restrict__ Whb,
                       const int* __restrict__ lens, const int* __restrict__ wid)
{
    extern __shared__ float sm[];
    float* Wp  = sm;            // [4g][8jp] rows of 516 (512 data + pad): 16512 floats
    float* Hsh = sm + 16512;    // [32 b] rows of 260: 8320 floats

    const int tid = threadIdx.x;
    const int d   = blockIdx.x >> 6;
    const int rem = blockIdx.x & 63;
    const int jb  = rem >> 2, bg = rem & 3;
    const int j0  = jb * 16, b0 = bg * 32;
    const float* __restrict__ Whh = d ? Whb : Whf;
    const float* __restrict__ P   = g_P + (size_t)d * V * 1024;

    // W_hh tile -> shared, j-pair interleaved: Wp[(g*8+jp)*516 + k*2 + (j&1)]
    for (int idx = tid; idx < 16384; idx += 128) {
        int g = idx >> 12, j = (idx >> 8) & 15, k = idx & 255;
        Wp[(size_t)(g * 8 + (j >> 1)) * 516 + k * 2 + (j & 1)] =
            Whh[(size_t)(g * H + j0 + j) * H + k];
    }

    const int jp = tid & 7, bq = tid >> 3;
    const int bA = b0 + bq * 2, bB = bA + 1;
    int maxlen = 0;
    for (int i = 0; i < 32; i++) { int L = lens[b0 + i]; if (L > maxlen) maxlen = L; }
    const int LA = lens[bA], LB = lens[bB];

    float cA0 = 0.f, cA1 = 0.f, cB0 = 0.f, cB1 = 0.f;
    const unsigned barid = d * 4 + bg;
    const int jcol = j0 + jp * 2;
    __syncthreads();

    for (int t = 0; t < maxlen; t++) {
        // prefetch gate pre-activations from P (L2 resident)
        float2 pxA0, pxA1, pxA2, pxA3, pxB0, pxB1, pxB2, pxB3;
        int posA = 0, posB = 0;
        const bool vA = (t < LA), vB = (t < LB);
        if (vA) {
            posA = d ? (LA - 1 - t) : t;
            const float2* p = (const float2*)(P + (size_t)wid[bA * T + posA] * 1024 + jcol);
            pxA0 = __ldg(p); pxA1 = __ldg(p + 128); pxA2 = __ldg(p + 256); pxA3 = __ldg(p + 384);
        }
        if (vB) {
            posB = d ? (LB - 1 - t) : t;
            const float2* p = (const float2*)(P + (size_t)wid[bB * T + posB] * 1024 + jcol);
            pxB0 = __ldg(p); pxB1 = __ldg(p + 128); pxB2 = __ldg(p + 256); pxB3 = __ldg(p + 384);
        }

        // h tile -> shared
        const int rb = t & 1;
        const float* hsrc = g_hstate + ((size_t)(rb * 2 + d) * B + b0) * H;
        #pragma unroll
        for (int q = 0; q < 16; q++) {
            int idx = tid + q * 128; int r = idx >> 6, c = idx & 63;
            float4 hv = __ldcg((const float4*)(hsrc + r * H + c * 4));
            *(float4*)&Hsh[r * 260 + c * 4] = hv;
        }
        __syncthreads();

        ull acc[4][2] = {{0ull, 0ull}, {0ull, 0ull}, {0ull, 0ull}, {0ull, 0ull}};
        const float* hrA = Hsh + (bq * 2) * 260;
        const float* hrB = Hsh + (bq * 2 + 1) * 260;
        const float* w0p = Wp + (size_t)(0 * 8 + jp) * 516;
        const float* w1p = Wp + (size_t)(1 * 8 + jp) * 516;
        const float* w2p = Wp + (size_t)(2 * 8 + jp) * 516;
        const float* w3p = Wp + (size_t)(3 * 8 + jp) * 516;

        #pragma unroll 4
        for (int kk = 0; kk < 256; kk += 2) {
            ulonglong2 w0 = *(const ulonglong2*)&w0p[kk * 2];
            ulonglong2 w1 = *(const ulonglong2*)&w1p[kk * 2];
            ulonglong2 w2 = *(const ulonglong2*)&w2p[kk * 2];
            ulonglong2 w3 = *(const ulonglong2*)&w3p[kk * 2];
            float2 hA = *(const float2*)&hrA[kk];
            float2 hB = *(const float2*)&hrB[kk];
            ull hA0 = pack2(hA.x, hA.x), hA1 = pack2(hA.y, hA.y);
            ull hB0 = pack2(hB.x, hB.x), hB1 = pack2(hB.y, hB.y);
            acc[0][0] = fma2(w0.x, hA0, acc[0][0]);
            acc[1][0] = fma2(w1.x, hA0, acc[1][0]);
            acc[2][0] = fma2(w2.x, hA0, acc[2][0]);
            acc[3][0] = fma2(w3.x, hA0, acc[3][0]);
            acc[0][1] = fma2(w0.x, hB0, acc[0][1]);
            acc[1][1] = fma2(w1.x, hB0, acc[1][1]);
            acc[2][1] = fma2(w2.x, hB0, acc[2][1]);
            acc[3][1] = fma2(w3.x, hB0, acc[3][1]);
            acc[0][0] = fma2(w0.y, hA1, acc[0][0]);
            acc[1][0] = fma2(w1.y, hA1, acc[1][0]);
            acc[2][0] = fma2(w2.y, hA1, acc[2][0]);
            acc[3][0] = fma2(w3.y, hA1, acc[3][0]);
            acc[0][1] = fma2(w0.y, hB1, acc[0][1]);
            acc[1][1] = fma2(w1.y, hB1, acc[1][1]);
            acc[2][1] = fma2(w2.y, hB1, acc[2][1]);
            acc[3][1] = fma2(w3.y, hB1, acc[3][1]);
        }

        const int wb = (t + 1) & 1;
        // batch A
        if (vA) {
            float i0, i1, f0, f1, gg0, gg1, o0, o1;
            unpack2(acc[0][0], i0, i1); unpack2(acc[1][0], f0, f1);
            unpack2(acc[2][0], gg0, gg1); unpack2(acc[3][0], o0, o1);
            i0 = sigf(i0 + pxA0.x);  i1 = sigf(i1 + pxA0.y);
            f0 = sigf(f0 + pxA1.x);  f1 = sigf(f1 + pxA1.y);
            gg0 = tanhf(gg0 + pxA2.x); gg1 = tanhf(gg1 + pxA2.y);
            o0 = sigf(o0 + pxA3.x);  o1 = sigf(o1 + pxA3.y);
            cA0 = f0 * cA0 + i0 * gg0; cA1 = f1 * cA1 + i1 * gg1;
            float2 hv; hv.x = o0 * tanhf(cA0); hv.y = o1 * tanhf(cA1);
            *(float2*)&g_hstate[((size_t)(wb * 2 + d) * B + bA) * H + jcol] = hv;
            int pos = d ? posA : t;
            *(float2*)&g_Hc[((size_t)bA * T + pos) * (2 * H) + d * H + jcol] = hv;
        }
        // batch B
        if (vB) {
            float i0, i1, f0, f1, gg0, gg1, o0, o1;
            unpack2(acc[0][1], i0, i1); unpack2(acc[1][1], f0, f1);
            unpack2(acc[2][1], gg0, gg1); unpack2(acc[3][1], o0, o1);
            i0 = sigf(i0 + pxB0.x);  i1 = sigf(i1 + pxB0.y);
            f0 = sigf(f0 + pxB1.x);  f1 = sigf(f1 + pxB1.y);
            gg0 = tanhf(gg0 + pxB2.x); gg1 = tanhf(gg1 + pxB2.y);
            o0 = sigf(o0 + pxB3.x);  o1 = sigf(o1 + pxB3.y);
            cB0 = f0 * cB0 + i0 * gg0; cB1 = f1 * cB1 + i1 * gg1;
            float2 hv; hv.x = o0 * tanhf(cB0); hv.y = o1 * tanhf(cB1);
            *(float2*)&g_hstate[((size_t)(wb * 2 + d) * B + bB) * H + jcol] = hv;
            int pos = d ? posB : t;
            *(float2*)&g_Hc[((size_t)bB * T + pos) * (2 * H) + d * H + jcol] = hv;
        }

        __threadfence();
        __syncthreads();
        if (tid == 0) {
            atomicAdd(&g_bar[barid], 1u);
            unsigned target = 16u * (unsigned)(t + 1);
            while (*((volatile unsigned*)&g_bar[barid]) < target) {}
            __threadfence();
        }
        __syncthreads();
    }
}

// ---------------- attention scores: s = tanh(Hc W_s1^T) W_s2^T ------
// block: 512 threads, 32 t-rows of one b; W_s1 in shared.
__global__ void k_scores(const float* __restrict__ Ws1, const float* __restrict__ Ws2)
{
    extern __shared__ float s2[];
    float* Ws  = s2;            // 25*512 = 12800
    float* raw = s2 + 12800;    // 32*25 = 800
    float* usm = s2 + 13600;    // 800

    const int tid = threadIdx.x;
    const int b  = blockIdx.x >> 4;
    const int t0 = (blockIdx.x & 15) * 32;

    for (int i = tid; i < 12800; i += 512) Ws[i] = Ws1[i];
    __syncthreads();

    const int wp = tid >> 5, lane = tid & 31;   // warp wp -> rows 2wp, 2wp+1
    float acc0[DA] = {}, acc1[DA] = {};
    const float* hc0 = g_Hc + ((size_t)b * T + t0 + wp * 2) * 512;
    #pragma unroll 4
    for (int kk = 0; kk < 16; kk++) {
        int k = lane + kk * 32;
        float h0 = hc0[k];
        float h1 = hc0[512 + k];
        #pragma unroll
        for (int a = 0; a < DA; a++) {
            float w = Ws[a * 512 + k];
            acc0[a] = fmaf(h0, w, acc0[a]);
            acc1[a] = fmaf(h1, w, acc1[a]);
        }
    }
    #pragma unroll
    for (int a = 0; a < DA; a++) {
        float v0 = acc0[a], v1 = acc1[a];
        #pragma unroll
        for (int off = 16; off; off >>= 1) {
            v0 += __shfl_xor_sync(0xffffffffu, v0, off);
            v1 += __shfl_xor_sync(0xffffffffu, v1, off);
        }
        if (lane == 0) {
            raw[(wp * 2 + 0) * DA + a] = v0;
            raw[(wp * 2 + 1) * DA + a] = v1;
        }
    }
    __syncthreads();
    for (int i = tid; i < 32 * DA; i += 512) usm[i] = tanhf(raw[i]);
    __syncthreads();
    if (tid < 32 * HEADS) {
        int r = tid / HEADS, h = tid % HEADS;
        float s = 0.f;
        #pragma unroll
        for (int a = 0; a < DA; a++) s = fmaf(usm[r * DA + a], __ldg(&Ws2[h * DA + a]), s);
        g_s[((size_t)b * HEADS + h) * T + t0 + r] = s;
    }
}

// ---------------- masked softmax over time, per (b,head) ------------
__global__ void k_softmax(const int* __restrict__ lens)
{
    int b = blockIdx.x / HEADS, h = blockIdx.x % HEADS;
    int t = threadIdx.x;               // 512
    int L = lens[b];
    __shared__ float red[512];
    float sv = (t < L) ? g_s[((size_t)b * HEADS + h) * T + t] : -3.0e38f;
    red[t] = sv; __syncthreads();
    for (int off = 256; off; off >>= 1) { if (t < off) red[t] = fmaxf(red[t], red[t + off]); __syncthreads(); }
    float m = red[0]; __syncthreads();
    float e = (t < L) ? expf(sv - m) : 0.0f;
    red[t] = e; __syncthreads();
    for (int off = 256; off; off >>= 1) { if (t < off) red[t] += red[t + off]; __syncthreads(); }
    g_A[((size_t)b * HEADS + h) * T + t] = e / red[0];
}

// ---------------- M = A @ Hc  ->  sentence embeddings ---------------
__global__ void k_M(float* __restrict__ out)
{
    int b = blockIdx.x;
    int d = threadIdx.x;               // 512
    __shared__ float As[HEADS * T];
    for (int i = d; i < HEADS * T; i += 512) As[i] = g_A[(size_t)b * HEADS * T + i];
    __syncthreads();
    float acc[HEADS] = {};
    const float* hcb = g_Hc + (size_t)b * T * 512;
    for (int t = 0; t < T; t++) {
        float hc = hcb[(size_t)t * 512 + d];
        #pragma unroll
        for (int h = 0; h < HEADS; h++) acc[h] = fmaf(As[h * T + t], hc, acc[h]);
    }
    #pragma unroll
    for (int h = 0; h < HEADS; h++)
        out[(size_t)b * (HEADS * 2 * H) + h * 512 + d] = acc[h];
}

// ---------------- penalty -------------------------------------------
__global__ void k_penal1()
{
    int b = blockIdx.x;
    int tid = threadIdx.x;             // 256
    __shared__ float As[HEADS * T];
    __shared__ float red[256];
    for (int i = tid; i < HEADS * T; i += 256) As[i] = g_A[(size_t)b * HEADS * T + i];
    __syncthreads();
    float tot = 0.0f;
    for (int h = 0; h < HEADS; h++) {
        for (int g = 0; g < HEADS; g++) {
            if (h == g) continue;
            float p = 0.0f;
            for (int t = tid; t < T; t += 256) p = fmaf(As[h * T + t], As[g * T + t], p);
            red[tid] = p; __syncthreads();
            for (int off = 128; off; off >>= 1) { if (tid < off) red[tid] += red[tid + off]; __syncthreads(); }
            if (tid == 0) tot += red[0] * red[0];
            __syncthreads();
        }
    }
    if (tid == 0) g_pp[b] = tot;
}

__global__ void k_penal2(float* __restrict__ out, int out_size)
{
    __shared__ float red[128];
    red[threadIdx.x] = g_pp[threadIdx.x];
    __syncthreads();
    for (int off = 64; off; off >>= 1) { if (threadIdx.x < off) red[threadIdx.x] += red[threadIdx.x + off]; __syncthreads(); }
    if (threadIdx.x == 0) out[out_size - 1] = red[0] / (float)B;
}

// ---------------- launch --------------------------------------------
extern "C" void kernel_launch(void* const* d_in, const int* in_sizes, int n_in,
                              void* d_out, int out_size)
{
    const int*   word_ids = (const int*)  d_in[0];
    const int*   lens     = (const int*)  d_in[1];
    const float* emb      = (const float*)d_in[2];
    const float* Wihf     = (const float*)d_in[3];
    const float* Whhf     = (const float*)d_in[4];
    const float* bf       = (const float*)d_in[5];
    const float* Wihb     = (const float*)d_in[6];
    const float* Whhb     = (const float*)d_in[7];
    const float* bb       = (const float*)d_in[8];
    const float* Ws1      = (const float*)d_in[9];
    const float* Ws2      = (const float*)d_in[10];
    float* out = (float*)d_out;

    k_init<<<2048, 256>>>();

    dim3 gP(16, (V + 63) / 64, 2);
    k_P<<<gP, 256>>>(emb, Wihf, bf, Wihb, bb);

    cudaFuncSetAttribute(k_lstm, cudaFuncAttributeMaxDynamicSharedMemorySize, 99328);
    k_lstm<<<128, 128, 99328>>>(Whhf, Whhb, lens, word_ids);

    cudaFuncSetAttribute(k_scores, cudaFuncAttributeMaxDynamicSharedMemorySize, 57600);
    k_scores<<<(B * T) / 32, 512, 57600>>>(Ws1, Ws2);

    k_softmax<<<B * HEADS, 512>>>(lens);
    k_M<<<B, 512>>>(out);
    k_penal1<<<B, 256>>>();
    k_penal2<<<1, 128>>>(out, out_size);
}